// round 11
// baseline (speedup 1.0000x reference)
#include <cuda_runtime.h>
#include <cuda_fp16.h>
#include <cstdint>
#include <cstddef>

#define SEQ 65536
#define HID 128
#define NG  512
#define INP 64

// x-gate scratch, slot = j*4 + gate (+2 steps padding for prefetch)
static __device__ float g_xg[(size_t)(SEQ + 2) * NG];

union F2U { float2 f; unsigned long long u; };

static __device__ __forceinline__ unsigned long long ld2(const float2* p) {
    F2U u; u.f = *p; return u.u;
}
static __device__ __forceinline__ unsigned long long ffma2(unsigned long long a,
                                                           unsigned long long b,
                                                           unsigned long long c) {
    unsigned long long d;
    asm("fma.rn.f32x2 %0, %1, %2, %3;" : "=l"(d) : "l"(a), "l"(b), "l"(c));
    return d;
}
static __device__ __forceinline__ unsigned long long fadd2(unsigned long long a,
                                                           unsigned long long b) {
    unsigned long long d;
    asm("add.rn.f32x2 %0, %1, %2;" : "=l"(d) : "l"(a), "l"(b));
    return d;
}
static __device__ __forceinline__ float hsum2(unsigned long long a) {
    F2U u; u.u = a; return u.f.x + u.f.y;
}
static __device__ __forceinline__ float ftanh(float x) {
    float y; asm("tanh.approx.f32 %0, %1;" : "=f"(y) : "f"(x)); return y;
}
static __device__ __forceinline__ float fsigm(float x) {
    return fmaf(0.5f, ftanh(0.5f * x), 0.5f);
}

#define MMA(d0, d1, d2, d3, a0, a1, a2, a3, b0, b1)                            \
    asm volatile(                                                              \
        "mma.sync.aligned.m16n8k16.row.col.f32.f16.f16.f32 "                   \
        "{%0,%1,%2,%3}, {%4,%5,%6,%7}, {%8,%9}, {%0,%1,%2,%3};"                \
        : "+f"(d0), "+f"(d1), "+f"(d2), "+f"(d3)                               \
        : "r"(a0), "r"(a1), "r"(a2), "r"(a3), "r"(b0), "r"(b1))

// ---------------------------------------------------------------------------
// Phase 1: x_gates with slot = j*4 + gate  (row r = gate*128 + j)
// ---------------------------------------------------------------------------
__global__ void __launch_bounds__(512, 1)
gemm_xg(const float* __restrict__ x, const float* __restrict__ Wih,
        const float* __restrict__ bih, const float* __restrict__ bhh)
{
    __shared__ __align__(16) float xs[128 * INP];
    const int r  = threadIdx.x;
    const int t0 = blockIdx.x * 128;

    {
        const float4* src = (const float4*)(x + (size_t)t0 * INP);
        float4* dst = (float4*)xs;
        #pragma unroll
        for (int i = r; i < 128 * INP / 4; i += 512) dst[i] = src[i];
    }

    unsigned long long w[32];
    {
        const float2* wr = (const float2*)(Wih + (size_t)r * INP);
        #pragma unroll
        for (int i = 0; i < 32; i++) w[i] = ld2(wr + i);
    }
    const float bias = bih[r] + bhh[r];
    const int slot = (r & 127) * 4 + (r >> 7);
    __syncthreads();

    for (int tt = 0; tt < 128; tt++) {
        const float2* xp = (const float2*)(xs + tt * INP);
        unsigned long long a0 = 0ull, a1 = 0ull, a2 = 0ull, a3 = 0ull;
        #pragma unroll
        for (int i = 0; i < 32; i += 4) {
            a0 = ffma2(w[i + 0], ld2(xp + i + 0), a0);
            a1 = ffma2(w[i + 1], ld2(xp + i + 1), a1);
            a2 = ffma2(w[i + 2], ld2(xp + i + 2), a2);
            a3 = ffma2(w[i + 3], ld2(xp + i + 3), a3);
        }
        g_xg[(size_t)(t0 + tt) * NG + slot] =
            hsum2(fadd2(fadd2(a0, a1), fadd2(a2, a3))) + bias;
    }
}

// ---------------------------------------------------------------------------
// Phase 2+3: single-CTA scan via warp-level HMMA (m16n8k16).
// 8 warps; warp w owns columns j in [16w, 16w+16). M-tile g = gate g's rows
// for those columns: A[g] = W_hh[g*128 + 16w + (0..15)][:], preloaded as
// fragments (128 half2 regs). B: h in column 0, cols 1..7 = 0.
// After 8 accumulating K-steps, lanes with lane%4==0 hold all 4 gates for
// columns j1=16w+r0 (d0) and j2=j1+8 (d2): no shuffles in the tail.
// ---------------------------------------------------------------------------
__global__ void __launch_bounds__(256, 1)
lstm_scan(const float* __restrict__ Whh,
          const float* __restrict__ Wlin,
          const float* __restrict__ blin,
          float* __restrict__ out)
{
    __shared__ __align__(16) __half h_s[2][HID];

    const int tid  = threadIdx.x;
    const int w_id = tid >> 5;
    const int lane = tid & 31;
    const int r0   = lane >> 2;        // row-in-tile 0..7
    const int kq   = lane & 3;         // col quad
    const int jb   = w_id * 16;        // column base
    const bool act = (kq == 0);        // lanes holding D column 0

    // A fragments: ha[gate][kstep][4] half2, loaded once from f32 gmem.
    __half2 ha[4][8][4];
    #pragma unroll
    for (int g = 0; g < 4; g++) {
        const float* rA = Whh + (size_t)(g * HID + jb + r0) * HID;
        const float* rB = Whh + (size_t)(g * HID + jb + r0 + 8) * HID;
        #pragma unroll
        for (int kk = 0; kk < 8; kk++) {
            const int c0 = kk * 16 + 2 * kq;
            ha[g][kk][0] = __float22half2_rn(*(const float2*)(rA + c0));
            ha[g][kk][1] = __float22half2_rn(*(const float2*)(rB + c0));
            ha[g][kk][2] = __float22half2_rn(*(const float2*)(rA + c0 + 8));
            ha[g][kk][3] = __float22half2_rn(*(const float2*)(rB + c0 + 8));
        }
    }

    if (tid < 2 * HID) ((__half*)h_s)[tid] = __float2half_rn(0.0f);

    float cA = 0.0f, cB = 0.0f;
    // xg: float4 per column j = 4 gates. Step stride = 128 float4.
    const float4* xb = (const float4*)g_xg + (jb + r0);
    float4 xA[2], xB[2];
    if (act) {
        xA[0] = xb[0];        xB[0] = xb[8];
        xA[1] = xb[NG / 4];   xB[1] = xb[NG / 4 + 8];
    }

    __syncthreads();

#define STEP(B)                                                                \
    {                                                                          \
        const __half* hs = h_s[(B) ^ 1];                                       \
        float d[4][4];                                                         \
        _Pragma("unroll")                                                      \
        for (int g = 0; g < 4; g++) {                                          \
            d[g][0] = 0.0f; d[g][1] = 0.0f; d[g][2] = 0.0f; d[g][3] = 0.0f;    \
        }                                                                      \
        _Pragma("unroll")                                                      \
        for (int kk = 0; kk < 8; kk++) {                                       \
            uint32_t b01 = 0u, b23 = 0u;                                       \
            if (lane < 4) {                                                    \
                b01 = *(const uint32_t*)(hs + kk * 16 + 2 * lane);             \
                b23 = *(const uint32_t*)(hs + kk * 16 + 2 * lane + 8);         \
            }                                                                  \
            _Pragma("unroll")                                                  \
            for (int g = 0; g < 4; g++) {                                      \
                MMA(d[g][0], d[g][1], d[g][2], d[g][3],                        \
                    *(const uint32_t*)&ha[g][kk][0],                           \
                    *(const uint32_t*)&ha[g][kk][1],                           \
                    *(const uint32_t*)&ha[g][kk][2],                           \
                    *(const uint32_t*)&ha[g][kk][3],                           \
                    b01, b23);                                                 \
            }                                                                  \
        }                                                                      \
        if (act) {                                                             \
            const float iA = fsigm(d[0][0] + xA[B].x);                         \
            const float fA = fsigm(d[1][0] + xA[B].y);                         \
            const float gA = ftanh(d[2][0] + xA[B].z);                         \
            const float oA = fsigm(d[3][0] + xA[B].w);                         \
            const float iB = fsigm(d[0][2] + xB[B].x);                         \
            const float fB = fsigm(d[1][2] + xB[B].y);                         \
            const float gB = ftanh(d[2][2] + xB[B].z);                         \
            const float oB = fsigm(d[3][2] + xB[B].w);                         \
            cA = fmaf(fA, cA, iA * gA);                                        \
            cB = fmaf(fB, cB, iB * gB);                                        \
            h_s[B][jb + r0]     = __float2half_rn(oA * ftanh(cA));             \
            h_s[B][jb + r0 + 8] = __float2half_rn(oB * ftanh(cB));             \
            xA[B] = xb[2 * (NG / 4)];                                          \
            xB[B] = xb[2 * (NG / 4) + 8];                                      \
            xb += NG / 4;                                                      \
        }                                                                      \
        __syncthreads();                                                       \
    }

    for (int t = 0; t < SEQ; t += 2) {
        STEP(0)
        STEP(1)
    }

    // h_T in h_s[1]; warp 0 reduces the linear head.
    if (tid < 32) {
        float s = 0.0f;
        #pragma unroll
        for (int m = 0; m < 4; m++)
            s += __half2float(h_s[1][lane + 32 * m]) * Wlin[lane + 32 * m];
        #pragma unroll
        for (int dd = 16; dd > 0; dd >>= 1)
            s += __shfl_xor_sync(0xffffffffu, s, dd);
        if (lane == 0)
            out[0] = fsigm(s + blin[0]);
    }
}

extern "C" void kernel_launch(void* const* d_in, const int* in_sizes, int n_in,
                              void* d_out, int out_size) {
    const float* input = (const float*)d_in[0];
    const float* Wih   = (const float*)d_in[1];
    const float* Whh   = (const float*)d_in[2];
    const float* bih   = (const float*)d_in[3];
    const float* bhh   = (const float*)d_in[4];
    const float* Wlin  = (const float*)d_in[5];
    const float* blin  = (const float*)d_in[6];
    float* out = (float*)d_out;

    gemm_xg<<<SEQ / 128, 512>>>(input, Wih, bih, bhh);
    lstm_scan<<<1, 256>>>(Whh, Wlin, blin, out);
}